// round 13
// baseline (speedup 1.0000x reference)
#include <cuda_runtime.h>
#include <cuda_bf16.h>
#include <cuda_fp16.h>
#include <stdint.h>

#define Bb 16
#define Qd 2048
#define Kd 2048
#define Fd 128
#define KT 64
#define NT 256

// kernel1 smem (words): QS[128][68] + KS[64][68] + MBA[256]
#define SMEM1_BYTES ((128*68 + 64*68 + 256)*4)
// kernel2 smem: VI interleaved hi/lo [32 kw][264]
#define SMEM2_BYTES (32*264*4)

#define PACKBF2(r, lo, hi) asm("cvt.rn.bf16x2.f32 %0, %1, %2;" : "=r"(r) : "f"(hi), "f"(lo))
#define EX2(d, x) asm("ex2.approx.f32 %0, %1;" : "=f"(d) : "f"(x))
#define SQRTA(d, x) asm("sqrt.approx.f32 %0, %1;" : "=f"(d) : "f"(x))

__device__ float    g_lsum[Bb * Qd];
__device__ __half   g_E[(size_t)256 * 32 * 8192];   // [cta][tile][warp*1024 + j*128 + lane*4]
__device__ uint32_t g_mb[(size_t)Bb * Qd * 64];     // or-mask bits: [row][64 words]

__device__ __forceinline__ void mma16816(float& c0, float& c1, float& c2, float& c3,
                                         uint32_t a0, uint32_t a1, uint32_t a2, uint32_t a3,
                                         uint32_t b0, uint32_t b1) {
    asm volatile("mma.sync.aligned.m16n8k16.row.col.f32.bf16.bf16.f32 "
        "{%0,%1,%2,%3}, {%4,%5,%6,%7}, {%8,%9}, {%0,%1,%2,%3};"
        : "+f"(c0), "+f"(c1), "+f"(c2), "+f"(c3)
        : "r"(a0), "r"(a1), "r"(a2), "r"(a3), "r"(b0), "r"(b1));
}

#define LDSM4(d0, d1, d2, d3, addr) \
    asm volatile("ldmatrix.sync.aligned.m8n8.x4.shared.b16 {%0,%1,%2,%3}, [%4];" \
        : "=r"(d0), "=r"(d1), "=r"(d2), "=r"(d3) : "r"(addr))

extern __shared__ uint32_t smw[];

// ---------------- kernel 1: S=QK^T, E=(am?0:exp(s/sqrt(128)-2))->g_E (fp16),
//                  lsum (unmasked) -> g_lsum, (am|alm) bits -> g_mb ----------------
__global__ void __launch_bounds__(NT, 1) lsum_kernel(
    const float* __restrict__ q, const float* __restrict__ k,
    const int* __restrict__ am, const int* __restrict__ alm)
{
    const int b = blockIdx.y, q0 = blockIdx.x * 128;
    const int cid = b * 16 + blockIdx.x;
    const int tid = threadIdx.x;
    const int wid = tid >> 5, lane = tid & 31;
    const int gid = lane >> 2, tig = lane & 3;

    uint32_t* QS  = smw;
    uint32_t* KS  = smw + 128 * 68;
    uint32_t* MBA = smw + 128 * 68 + 64 * 68;

    const float C1 = 0.12753859788f;    // log2(e)/sqrt(128)
    const float C0 = -2.88539008178f;   // -2*log2(e)

    {
        const float* qp = q + ((size_t)b * Qd + q0) * Fd;
        #pragma unroll
        for (int it = 0; it < 16; it++) {
            int widx = tid + it * 256;
            int row = widx >> 5, w4 = widx & 31;
            float4 t = *(const float4*)(qp + row * Fd + 4 * w4);
            uint32_t p0, p1;
            PACKBF2(p0, t.x, t.y);
            PACKBF2(p1, t.z, t.w);
            *(uint2*)(QS + row * 68 + 2 * w4) = make_uint2(p0, p1);
        }
    }

    const int lm = lane >> 3, lr = lane & 7;
    const uint32_t qsb = (uint32_t)__cvta_generic_to_shared(QS);
    const uint32_t ksb = (uint32_t)__cvta_generic_to_shared(KS);
    const uint32_t aAddr0 = qsb + (((wid * 16 + ((lm & 1) << 3) + lr) * 68) + ((lm >> 1) << 2)) * 4;
    const uint32_t bAddr0 = ksb + (((((lm >> 1) << 3) + lr) * 68) + ((lm & 1) << 2)) * 4;

    const int r0l = wid * 16 + gid;
    const int mrow = tid >> 1, mhalf = tid & 1;
    const int* amp_base = am  + ((size_t)b * Qd + q0 + mrow) * Kd + mhalf * 32;
    const int* alp_base = alm + ((size_t)b * Qd + q0 + mrow) * Kd + mhalf * 32;
    uint32_t* mb_out = g_mb + ((size_t)b * Qd + q0 + mrow) * 64 + mhalf;

    float lsum0 = 0.f, lsum1 = 0.f;

    for (int t = 0; t < 32; t++) {
        const int k0 = t * KT;
        {
            const float* kp = k + ((size_t)b * Kd + k0) * Fd;
            #pragma unroll
            for (int it = 0; it < 8; it++) {
                int widx = tid + it * 256;
                int row = widx >> 5, w4 = widx & 31;
                float4 tt = *(const float4*)(kp + row * Fd + 4 * w4);
                uint32_t p0, p1;
                PACKBF2(p0, tt.x, tt.y);
                PACKBF2(p1, tt.z, tt.w);
                *(uint2*)(KS + row * 68 + 2 * w4) = make_uint2(p0, p1);
            }
        }
        // pack masks: am bits -> smem (for E masking), (am|alm) bits -> global
        {
            const int4* amp = (const int4*)(amp_base + k0);
            const int4* alp = (const int4*)(alp_base + k0);
            uint32_t wa = 0, wo = 0;
            #pragma unroll
            for (int i = 0; i < 8; i++) {
                int4 ma = amp[i];
                int4 ml = alp[i];
                uint32_t ba = (uint32_t)(ma.x | (ma.y << 1) | (ma.z << 2) | (ma.w << 3));
                uint32_t bo = (uint32_t)((ma.x | ml.x) | ((ma.y | ml.y) << 1) |
                                         ((ma.z | ml.z) << 2) | ((ma.w | ml.w) << 3));
                wa |= ba << (4 * i);
                wo |= bo << (4 * i);
            }
            MBA[mrow * 2 + mhalf] = wa;
            mb_out[t * 2] = wo;
        }
        __syncthreads();

        float sc[8][4];
        #pragma unroll
        for (int j = 0; j < 8; j++)
            #pragma unroll
            for (int c = 0; c < 4; c++) sc[j][c] = 0.f;

        #pragma unroll
        for (int ks = 0; ks < 8; ks++) {
            uint32_t a0, a1, a2, a3;
            LDSM4(a0, a1, a2, a3, aAddr0 + ks * 32);
            #pragma unroll
            for (int jp = 0; jp < 4; jp++) {
                uint32_t b0, b1, b2, b3;
                LDSM4(b0, b1, b2, b3, bAddr0 + jp * (16 * 68 * 4) + ks * 32);
                mma16816(sc[2*jp][0], sc[2*jp][1], sc[2*jp][2], sc[2*jp][3],
                         a0, a1, a2, a3, b0, b1);
                mma16816(sc[2*jp+1][0], sc[2*jp+1][1], sc[2*jp+1][2], sc[2*jp+1][3],
                         a0, a1, a2, a3, b2, b3);
            }
        }

        uint2 mw0 = *(const uint2*)(MBA + r0l * 2);
        uint2 mw1 = *(const uint2*)(MBA + (r0l + 8) * 2);

        const size_t eb = (((size_t)cid * 32 + t) * 8 + wid) * 1024 + lane * 4;
        #pragma unroll
        for (int j = 0; j < 8; j++) {
            float e0, e1, e2, e3;
            EX2(e0, fmaf(sc[j][0], C1, C0));
            EX2(e1, fmaf(sc[j][1], C1, C0));
            EX2(e2, fmaf(sc[j][2], C1, C0));
            EX2(e3, fmaf(sc[j][3], C1, C0));
            lsum0 += e0 + e1;                       // denominator: unmasked
            lsum1 += e2 + e3;
            const int sh = (j & 3) * 8 + tig * 2;
            const uint32_t w0 = (j < 4) ? mw0.x : mw0.y;
            const uint32_t w1 = (j < 4) ? mw1.x : mw1.y;
            float e0m = ((w0 >> sh) & 1)       ? 0.f : e0;
            float e1m = ((w0 >> (sh + 1)) & 1) ? 0.f : e1;
            float e2m = ((w1 >> sh) & 1)       ? 0.f : e2;
            float e3m = ((w1 >> (sh + 1)) & 1) ? 0.f : e3;
            __half2 hA = __floats2half2_rn(e0m, e1m);
            __half2 hB = __floats2half2_rn(e2m, e3m);
            uint2 u;
            u.x = *(uint32_t*)&hA;
            u.y = *(uint32_t*)&hB;
            *(uint2*)&g_E[eb + j * 128] = u;
        }
        __syncthreads();
    }

    lsum0 += __shfl_xor_sync(0xffffffffu, lsum0, 1);
    lsum0 += __shfl_xor_sync(0xffffffffu, lsum0, 2);
    lsum1 += __shfl_xor_sync(0xffffffffu, lsum1, 1);
    lsum1 += __shfl_xor_sync(0xffffffffu, lsum1, 2);
    if (tig == 0) {
        g_lsum[(size_t)b * Qd + q0 + r0l] = lsum0;
        g_lsum[(size_t)b * Qd + q0 + r0l + 8] = lsum1;
    }
}

// ---------------- kernel 2: P = E*inv - (bit?0:dist), O = P @ V ----------------
__global__ void __launch_bounds__(NT, 2) alibi_main_kernel(
    const float* __restrict__ v,
    const float* __restrict__ cq, const float* __restrict__ ck,
    const float* __restrict__ bias_scale, const float* __restrict__ running_mean,
    float* __restrict__ out)
{
    const int b = blockIdx.y, q0 = blockIdx.x * 128;
    const int cid = b * 16 + blockIdx.x;
    const int tid = threadIdx.x;
    const int wid = tid >> 5, lane = tid & 31;
    const int gid = lane >> 2, tig = lane & 3;

    uint32_t* VI = smw;

    const float dscale = bias_scale[0] / running_mean[0];

    const int r0l = wid * 16 + gid;
    const size_t r0g = (size_t)b * Qd + q0 + r0l;
    const size_t r1g = r0g + 8;
    const float cqx0 = cq[2 * r0g], cqy0 = cq[2 * r0g + 1];
    const float cqx1 = cq[2 * r1g], cqy1 = cq[2 * r1g + 1];
    const float inv0 = 1.f / g_lsum[r0g];
    const float inv1 = 1.f / g_lsum[r1g];
    const uint32_t* mb0 = g_mb + r0g * 64;
    const uint32_t* mb1 = g_mb + r1g * 64;

    float acc[16][4];
    #pragma unroll
    for (int jn = 0; jn < 16; jn++)
        #pragma unroll
        for (int c = 0; c < 4; c++) acc[jn][c] = 0.f;

    for (int t = 0; t < 32; t++) {
        const int k0 = t * KT;

        uint2 Eu[8];
        {
            const size_t eb = (((size_t)cid * 32 + t) * 8 + wid) * 1024 + lane * 4;
            #pragma unroll
            for (int j = 0; j < 8; j++)
                Eu[j] = *(const uint2*)&g_E[eb + j * 128];
        }
        uint2 o0w = *(const uint2*)(mb0 + t * 2);
        uint2 o1w = *(const uint2*)(mb1 + t * 2);

        {
            const float* vp = v + ((size_t)b * Kd + k0) * Fd;
            #pragma unroll
            for (int it = 0; it < 4; it++) {
                int idx = tid + it * 256;
                int fq = idx & 31, kw = idx >> 5;
                const float* va = vp + (size_t)(2 * kw) * Fd + 4 * fq;
                float4 a = *(const float4*)va;
                float4 bb = *(const float4*)(va + Fd);
                uint32_t ph0, ph1, ph2, ph3;
                PACKBF2(ph0, a.x, bb.x);
                PACKBF2(ph1, a.y, bb.y);
                PACKBF2(ph2, a.z, bb.z);
                PACKBF2(ph3, a.w, bb.w);
                uint32_t pl0, pl1, pl2, pl3;
                float r0, r1;
                r0 = a.x - __uint_as_float(ph0 << 16); r1 = bb.x - __uint_as_float(ph0 & 0xffff0000u);
                PACKBF2(pl0, r0, r1);
                r0 = a.y - __uint_as_float(ph1 << 16); r1 = bb.y - __uint_as_float(ph1 & 0xffff0000u);
                PACKBF2(pl1, r0, r1);
                r0 = a.z - __uint_as_float(ph2 << 16); r1 = bb.z - __uint_as_float(ph2 & 0xffff0000u);
                PACKBF2(pl2, r0, r1);
                r0 = a.w - __uint_as_float(ph3 << 16); r1 = bb.w - __uint_as_float(ph3 & 0xffff0000u);
                PACKBF2(pl3, r0, r1);
                int base = kw * 264 + 8 * fq;
                *(uint4*)(VI + base)     = make_uint4(ph0, pl0, ph1, pl1);
                *(uint4*)(VI + base + 4) = make_uint4(ph2, pl2, ph3, pl3);
            }
        }
        __syncthreads();

        #pragma unroll
        for (int ks = 0; ks < 4; ks++) {
            uint32_t HA0, HA1, HB0, HB1, LA0, LA1, LB0, LB1;
            #pragma unroll
            for (int jj = 0; jj < 2; jj++) {
                int j = 2 * ks + jj;
                int c0 = k0 + j * 8 + tig * 2;
                float4 ckv = *(const float4*)(ck + ((size_t)b * Kd + c0) * 2);

                const int sh = (j & 3) * 8 + tig * 2;
                const uint32_t wo0 = (j < 4) ? o0w.x : o0w.y;
                const uint32_t wo1 = (j < 4) ? o1w.x : o1w.y;

                float2 fA = __half22float2(*(__half2*)&Eu[j].x);
                float2 fB = __half22float2(*(__half2*)&Eu[j].y);

                float dxa = cqx0 - ckv.x, dya = cqy0 - ckv.y;
                float dxb = cqx0 - ckv.z, dyb = cqy0 - ckv.w;
                float dxc = cqx1 - ckv.x, dyc = cqy1 - ckv.y;
                float dxd = cqx1 - ckv.z, dyd = cqy1 - ckv.w;
                float d00, d01, d10, d11;
                SQRTA(d00, fmaf(dxa, dxa, dya * dya));
                SQRTA(d01, fmaf(dxb, dxb, dyb * dyb));
                SQRTA(d10, fmaf(dxc, dxc, dyc * dyc));
                SQRTA(d11, fmaf(dxd, dxd, dyd * dyd));

                d00 = ((wo0 >> sh) & 1)       ? 0.f : d00 * dscale;
                d01 = ((wo0 >> (sh + 1)) & 1) ? 0.f : d01 * dscale;
                d10 = ((wo1 >> sh) & 1)       ? 0.f : d10 * dscale;
                d11 = ((wo1 >> (sh + 1)) & 1) ? 0.f : d11 * dscale;

                float p00 = fA.x * inv0 - d00;
                float p01 = fA.y * inv0 - d01;
                float p10 = fB.x * inv1 - d10;
                float p11 = fB.y * inv1 - d11;

                uint32_t h0, h1, l0, l1;
                PACKBF2(h0, p00, p01);
                PACKBF2(h1, p10, p11);
                float q00 = p00 - __uint_as_float(h0 << 16);
                float q01 = p01 - __uint_as_float(h0 & 0xffff0000u);
                float q10 = p10 - __uint_as_float(h1 << 16);
                float q11 = p11 - __uint_as_float(h1 & 0xffff0000u);
                PACKBF2(l0, q00, q01);
                PACKBF2(l1, q10, q11);
                if (jj == 0) { HA0 = h0; HA1 = h1; LA0 = l0; LA1 = l1; }
                else         { HB0 = h0; HB1 = h1; LB0 = l0; LB1 = l1; }
            }

            const int vbase = tig * 264 + ks * 2112;
            #pragma unroll
            for (int jn = 0; jn < 16; jn++) {
                int a = vbase + (jn * 8 + gid) * 2;
                uint2 u2a = *(const uint2*)(VI + a);
                uint2 u2b = *(const uint2*)(VI + a + 1056);
                mma16816(acc[jn][0], acc[jn][1], acc[jn][2], acc[jn][3],
                         HA0, HA1, HB0, HB1, u2a.x, u2b.x);
                mma16816(acc[jn][0], acc[jn][1], acc[jn][2], acc[jn][3],
                         HA0, HA1, HB0, HB1, u2a.y, u2b.y);
                mma16816(acc[jn][0], acc[jn][1], acc[jn][2], acc[jn][3],
                         LA0, LA1, LB0, LB1, u2a.x, u2b.x);
            }
        }
        __syncthreads();
    }

    float* o0 = out + r0g * Fd + tig * 2;
    float* o1 = out + r1g * Fd + tig * 2;
    #pragma unroll
    for (int jn = 0; jn < 16; jn++) {
        *(float2*)(o0 + jn * 8) = make_float2(acc[jn][0], acc[jn][1]);
        *(float2*)(o1 + jn * 8) = make_float2(acc[jn][2], acc[jn][3]);
    }
}

extern "C" void kernel_launch(void* const* d_in, const int* in_sizes, int n_in,
                              void* d_out, int out_size) {
    const float* q   = (const float*)d_in[0];
    const float* k   = (const float*)d_in[1];
    const float* v   = (const float*)d_in[2];
    const float* cq  = (const float*)d_in[3];
    const float* ck  = (const float*)d_in[4];
    const int* am    = (const int*)d_in[5];
    const int* alm   = (const int*)d_in[6];
    const float* bs  = (const float*)d_in[7];
    const float* rm  = (const float*)d_in[8];
    float* out = (float*)d_out;

    cudaFuncSetAttribute(lsum_kernel,
                         cudaFuncAttributeMaxDynamicSharedMemorySize, SMEM1_BYTES);
    cudaFuncSetAttribute(alibi_main_kernel,
                         cudaFuncAttributeMaxDynamicSharedMemorySize, SMEM2_BYTES);

    dim3 grid(Qd / 128, Bb);
    lsum_kernel<<<grid, NT, SMEM1_BYTES>>>(q, k, am, alm);
    alibi_main_kernel<<<grid, NT, SMEM2_BYTES>>>(v, cq, ck, bs, rm, out);
}

// round 14
// speedup vs baseline: 1.3706x; 1.3706x over previous
#include <cuda_runtime.h>
#include <cuda_bf16.h>
#include <cuda_fp16.h>
#include <stdint.h>

#define Bb 16
#define Qd 2048
#define Kd 2048
#define Fd 128
#define KT 64
#define NT 256

// kernel1 smem (words): QS[128][68] + KS[64][68]
#define SMEM1_BYTES ((128*68 + 64*68)*4)
// kernel2 smem: VI blocked frag layout: 64 blocks x 132 words
#define SMEM2_BYTES (64*132*4)

#define PACKBF2(r, lo, hi) asm("cvt.rn.bf16x2.f32 %0, %1, %2;" : "=r"(r) : "f"(hi), "f"(lo))
#define EX2(d, x) asm("ex2.approx.f32 %0, %1;" : "=f"(d) : "f"(x))
#define SQRTA(d, x) asm("sqrt.approx.f32 %0, %1;" : "=f"(d) : "f"(x))

__device__ float  g_lsum[Bb * Qd];
__device__ __half g_E[(size_t)256 * 32 * 8192];   // [cta][tile][warp][lane*32 + j*4] halves

__device__ __forceinline__ void mma16816(float& c0, float& c1, float& c2, float& c3,
                                         uint32_t a0, uint32_t a1, uint32_t a2, uint32_t a3,
                                         uint32_t b0, uint32_t b1) {
    asm volatile("mma.sync.aligned.m16n8k16.row.col.f32.bf16.bf16.f32 "
        "{%0,%1,%2,%3}, {%4,%5,%6,%7}, {%8,%9}, {%0,%1,%2,%3};"
        : "+f"(c0), "+f"(c1), "+f"(c2), "+f"(c3)
        : "r"(a0), "r"(a1), "r"(a2), "r"(a3), "r"(b0), "r"(b1));
}

#define LDSM4(d0, d1, d2, d3, addr) \
    asm volatile("ldmatrix.sync.aligned.m8n8.x4.shared.b16 {%0,%1,%2,%3}, [%4];" \
        : "=r"(d0), "=r"(d1), "=r"(d2), "=r"(d3) : "r"(addr))

extern __shared__ uint32_t smw[];

// ---------------- kernel 1: S = QK^T, E = exp(s/sqrt(128) - 2) -> g_E, row sums -> g_lsum ----------------
__global__ void __launch_bounds__(NT, 1) lsum_kernel(
    const float* __restrict__ q, const float* __restrict__ k)
{
    const int b = blockIdx.y, q0 = blockIdx.x * 128;
    const int cid = b * 16 + blockIdx.x;
    const int tid = threadIdx.x;
    const int wid = tid >> 5, lane = tid & 31;
    const int gid = lane >> 2, tig = lane & 3;

    uint32_t* QS = smw;
    uint32_t* KS = smw + 128 * 68;

    const float C1 = 0.12753859788f;    // log2(e)/sqrt(128)
    const float C0 = -2.88539008178f;   // -2*log2(e)

    {
        const float* qp = q + ((size_t)b * Qd + q0) * Fd;
        #pragma unroll
        for (int it = 0; it < 16; it++) {
            int widx = tid + it * 256;
            int row = widx >> 5, w4 = widx & 31;
            float4 t = *(const float4*)(qp + row * Fd + 4 * w4);
            uint32_t p0, p1;
            PACKBF2(p0, t.x, t.y);
            PACKBF2(p1, t.z, t.w);
            *(uint2*)(QS + row * 68 + 2 * w4) = make_uint2(p0, p1);
        }
    }

    const int lm = lane >> 3, lr = lane & 7;
    const uint32_t qsb = (uint32_t)__cvta_generic_to_shared(QS);
    const uint32_t ksb = (uint32_t)__cvta_generic_to_shared(KS);
    const uint32_t aAddr0 = qsb + (((wid * 16 + ((lm & 1) << 3) + lr) * 68) + ((lm >> 1) << 2)) * 4;
    const uint32_t bAddr0 = ksb + (((((lm >> 1) << 3) + lr) * 68) + ((lm & 1) << 2)) * 4;

    float lsum0 = 0.f, lsum1 = 0.f;

    for (int t = 0; t < 32; t++) {
        const int k0 = t * KT;
        {
            const float* kp = k + ((size_t)b * Kd + k0) * Fd;
            #pragma unroll
            for (int it = 0; it < 8; it++) {
                int widx = tid + it * 256;
                int row = widx >> 5, w4 = widx & 31;
                float4 tt = *(const float4*)(kp + row * Fd + 4 * w4);
                uint32_t p0, p1;
                PACKBF2(p0, tt.x, tt.y);
                PACKBF2(p1, tt.z, tt.w);
                *(uint2*)(KS + row * 68 + 2 * w4) = make_uint2(p0, p1);
            }
        }
        __syncthreads();

        float sc[8][4];
        #pragma unroll
        for (int j = 0; j < 8; j++)
            #pragma unroll
            for (int c = 0; c < 4; c++) sc[j][c] = 0.f;

        #pragma unroll
        for (int ks = 0; ks < 8; ks++) {
            uint32_t a0, a1, a2, a3;
            LDSM4(a0, a1, a2, a3, aAddr0 + ks * 32);
            #pragma unroll
            for (int jp = 0; jp < 4; jp++) {
                uint32_t b0, b1, b2, b3;
                LDSM4(b0, b1, b2, b3, bAddr0 + jp * (16 * 68 * 4) + ks * 32);
                mma16816(sc[2*jp][0], sc[2*jp][1], sc[2*jp][2], sc[2*jp][3],
                         a0, a1, a2, a3, b0, b1);
                mma16816(sc[2*jp+1][0], sc[2*jp+1][1], sc[2*jp+1][2], sc[2*jp+1][3],
                         a0, a1, a2, a3, b2, b3);
            }
        }

        uint32_t Ebuf[16];
        #pragma unroll
        for (int j = 0; j < 8; j++) {
            float e0, e1, e2, e3;
            EX2(e0, fmaf(sc[j][0], C1, C0));
            EX2(e1, fmaf(sc[j][1], C1, C0));
            EX2(e2, fmaf(sc[j][2], C1, C0));
            EX2(e3, fmaf(sc[j][3], C1, C0));
            lsum0 += e0 + e1;
            lsum1 += e2 + e3;
            __half2 hA = __floats2half2_rn(e0, e1);
            __half2 hB = __floats2half2_rn(e2, e3);
            Ebuf[2*j]   = *(uint32_t*)&hA;
            Ebuf[2*j+1] = *(uint32_t*)&hB;
        }
        {
            const size_t eb = (((size_t)cid * 32 + t) * 8 + wid) * 1024 + lane * 32;
            uint4* ep = (uint4*)&g_E[eb];
            const uint4* sp = (const uint4*)Ebuf;
            ep[0] = sp[0]; ep[1] = sp[1]; ep[2] = sp[2]; ep[3] = sp[3];
        }
        __syncthreads();
    }

    lsum0 += __shfl_xor_sync(0xffffffffu, lsum0, 1);
    lsum0 += __shfl_xor_sync(0xffffffffu, lsum0, 2);
    lsum1 += __shfl_xor_sync(0xffffffffu, lsum1, 1);
    lsum1 += __shfl_xor_sync(0xffffffffu, lsum1, 2);
    if (tig == 0) {
        g_lsum[(size_t)b * Qd + q0 + wid * 16 + gid] = lsum0;
        g_lsum[(size_t)b * Qd + q0 + wid * 16 + gid + 8] = lsum1;
    }
}

// ---------------- kernel 2: P = (am?0:E*inv) - (or?0:dist), O = P @ V ----------------
__global__ void __launch_bounds__(NT, 2) alibi_main_kernel(
    const float* __restrict__ v,
    const float* __restrict__ cq, const float* __restrict__ ck,
    const int* __restrict__ am, const int* __restrict__ alm,
    const float* __restrict__ bias_scale, const float* __restrict__ running_mean,
    float* __restrict__ out)
{
    const int b = blockIdx.y, q0 = blockIdx.x * 128;
    const int cid = b * 16 + blockIdx.x;
    const int tid = threadIdx.x;
    const int wid = tid >> 5, lane = tid & 31;
    const int gid = lane >> 2, tig = lane & 3;

    uint32_t* VI = smw;

    const float dscale = bias_scale[0] / running_mean[0];

    const int r0l = wid * 16 + gid;
    const size_t r0g = (size_t)b * Qd + q0 + r0l;
    const size_t r1g = r0g + 8;
    const float cqx0 = cq[2 * r0g], cqy0 = cq[2 * r0g + 1];
    const float cqx1 = cq[2 * r1g], cqy1 = cq[2 * r1g + 1];
    const size_t m0 = r0g * (size_t)Kd, m1 = r1g * (size_t)Kd;
    const float inv0 = 1.f / g_lsum[r0g];
    const float inv1 = 1.f / g_lsum[r1g];

    float acc[16][4];
    #pragma unroll
    for (int jn = 0; jn < 16; jn++)
        #pragma unroll
        for (int c = 0; c < 4; c++) acc[jn][c] = 0.f;

    const int vfrag = tig * 4 + gid * 16;   // within-block word offset (consumer)

    for (int t = 0; t < 32; t++) {
        const int k0 = t * KT;

        // E fragments for this tile: 4 x LDG.128
        uint32_t Er[16];
        {
            const size_t eb = (((size_t)cid * 32 + t) * 8 + wid) * 1024 + lane * 32;
            const uint4* ep = (const uint4*)&g_E[eb];
            uint4* dp = (uint4*)Er;
            dp[0] = ep[0]; dp[1] = ep[1]; dp[2] = ep[2]; dp[3] = ep[3];
        }

        // V frag-layout fill: block (ks,jn) = 132 words; word = blk + gid*16 + tig*4
        // uint4 per (jn,ks,gid,tig) = (bh0, bl0, bh1, bl1): b0 = k rows (2tig,2tig+1), b1 = +8
        {
            const float* vp = v + ((size_t)b * Kd + k0) * Fd;
            #pragma unroll
            for (int it = 0; it < 2; it++) {
                int idx = tid + it * 256;          // 0..511
                int gidh = idx & 1;
                int jnw  = (idx >> 1) & 15;
                int tigw = (idx >> 5) & 3;
                int ksw  = idx >> 7;
                int k0r  = ksw * 16 + tigw * 2;
                const float* vb = vp + (size_t)k0r * Fd + jnw * 8 + gidh * 4;
                float4 vA0 = *(const float4*)(vb);
                float4 vA1 = *(const float4*)(vb + Fd);
                float4 vB0 = *(const float4*)(vb + 8 * Fd);
                float4 vB1 = *(const float4*)(vb + 9 * Fd);
                int blk = (ksw * 16 + jnw) * 132 + tigw * 4;
                const float* a0p = &vA0.x; const float* a1p = &vA1.x;
                const float* b0p = &vB0.x; const float* b1p = &vB1.x;
                #pragma unroll
                for (int c = 0; c < 4; c++) {
                    uint32_t pha, phb, pla, plb;
                    PACKBF2(pha, a0p[c], a1p[c]);
                    PACKBF2(phb, b0p[c], b1p[c]);
                    float ra0 = a0p[c] - __uint_as_float(pha << 16);
                    float ra1 = a1p[c] - __uint_as_float(pha & 0xffff0000u);
                    PACKBF2(pla, ra0, ra1);
                    float rb0 = b0p[c] - __uint_as_float(phb << 16);
                    float rb1 = b1p[c] - __uint_as_float(phb & 0xffff0000u);
                    PACKBF2(plb, rb0, rb1);
                    *(uint4*)(VI + blk + (gidh * 4 + c) * 16) = make_uint4(pha, pla, phb, plb);
                }
            }
        }
        __syncthreads();

        // ---- per k16-chunk: elementwise P, then PV ----
        #pragma unroll
        for (int ks = 0; ks < 4; ks++) {
            uint32_t HA0, HA1, HB0, HB1, LA0, LA1, LB0, LB1;
            #pragma unroll
            for (int jj = 0; jj < 2; jj++) {
                int j = 2 * ks + jj;
                int c0 = k0 + j * 8 + tig * 2;
                float4 ckv = *(const float4*)(ck + ((size_t)b * Kd + c0) * 2);
                int2 a0m = *(const int2*)(am  + m0 + c0);
                int2 a1m = *(const int2*)(am  + m1 + c0);
                int2 l0m = *(const int2*)(alm + m0 + c0);
                int2 l1m = *(const int2*)(alm + m1 + c0);

                float2 fA = __half22float2(*(__half2*)&Er[2*j]);
                float2 fB = __half22float2(*(__half2*)&Er[2*j+1]);
                float e00 = fA.x, e01 = fA.y, e10 = fB.x, e11 = fB.y;

                float dxa = cqx0 - ckv.x, dya = cqy0 - ckv.y;
                float dxb = cqx0 - ckv.z, dyb = cqy0 - ckv.w;
                float dxc = cqx1 - ckv.x, dyc = cqy1 - ckv.y;
                float dxd = cqx1 - ckv.z, dyd = cqy1 - ckv.w;
                float d00, d01, d10, d11;
                SQRTA(d00, fmaf(dxa, dxa, dya * dya));
                SQRTA(d01, fmaf(dxb, dxb, dyb * dyb));
                SQRTA(d10, fmaf(dxc, dxc, dyc * dyc));
                SQRTA(d11, fmaf(dxd, dxd, dyd * dyd));

                d00 = (a0m.x | l0m.x) ? 0.f : d00 * dscale;
                d01 = (a0m.y | l0m.y) ? 0.f : d01 * dscale;
                d10 = (a1m.x | l1m.x) ? 0.f : d10 * dscale;
                d11 = (a1m.y | l1m.y) ? 0.f : d11 * dscale;

                float p00 = (a0m.x ? 0.f : e00 * inv0) - d00;
                float p01 = (a0m.y ? 0.f : e01 * inv0) - d01;
                float p10 = (a1m.x ? 0.f : e10 * inv1) - d10;
                float p11 = (a1m.y ? 0.f : e11 * inv1) - d11;

                uint32_t h0, h1, l0, l1;
                PACKBF2(h0, p00, p01);
                PACKBF2(h1, p10, p11);
                float q00 = p00 - __uint_as_float(h0 << 16);
                float q01 = p01 - __uint_as_float(h0 & 0xffff0000u);
                float q10 = p10 - __uint_as_float(h1 << 16);
                float q11 = p11 - __uint_as_float(h1 & 0xffff0000u);
                PACKBF2(l0, q00, q01);
                PACKBF2(l1, q10, q11);
                if (jj == 0) { HA0 = h0; HA1 = h1; LA0 = l0; LA1 = l1; }
                else         { HB0 = h0; HB1 = h1; LB0 = l0; LB1 = l1; }
            }

            #pragma unroll
            for (int jn = 0; jn < 16; jn++) {
                uint4 u = *(const uint4*)(VI + (ks * 16 + jn) * 132 + vfrag);
                mma16816(acc[jn][0], acc[jn][1], acc[jn][2], acc[jn][3],
                         HA0, HA1, HB0, HB1, u.x, u.z);
                mma16816(acc[jn][0], acc[jn][1], acc[jn][2], acc[jn][3],
                         HA0, HA1, HB0, HB1, u.y, u.w);
                mma16816(acc[jn][0], acc[jn][1], acc[jn][2], acc[jn][3],
                         LA0, LA1, LB0, LB1, u.x, u.z);
            }
        }
        __syncthreads();
    }

    float* o0 = out + r0g * Fd + tig * 2;
    float* o1 = out + r1g * Fd + tig * 2;
    #pragma unroll
    for (int jn = 0; jn < 16; jn++) {
        *(float2*)(o0 + jn * 8) = make_float2(acc[jn][0], acc[jn][1]);
        *(float2*)(o1 + jn * 8) = make_float2(acc[jn][2], acc[jn][3]);
    }
}

extern "C" void kernel_launch(void* const* d_in, const int* in_sizes, int n_in,
                              void* d_out, int out_size) {
    const float* q   = (const float*)d_in[0];
    const float* k   = (const float*)d_in[1];
    const float* v   = (const float*)d_in[2];
    const float* cq  = (const float*)d_in[3];
    const float* ck  = (const float*)d_in[4];
    const int* am    = (const int*)d_in[5];
    const int* alm   = (const int*)d_in[6];
    const float* bs  = (const float*)d_in[7];
    const float* rm  = (const float*)d_in[8];
    float* out = (float*)d_out;

    cudaFuncSetAttribute(lsum_kernel,
                         cudaFuncAttributeMaxDynamicSharedMemorySize, SMEM1_BYTES);
    cudaFuncSetAttribute(alibi_main_kernel,
                         cudaFuncAttributeMaxDynamicSharedMemorySize, SMEM2_BYTES);

    dim3 grid(Qd / 128, Bb);
    lsum_kernel<<<grid, NT, SMEM1_BYTES>>>(q, k);
    alibi_main_kernel<<<grid, NT, SMEM2_BYTES>>>(v, cq, ck, am, alm, bs, rm, out);
}